// round 2
// baseline (speedup 1.0000x reference)
#include <cuda_runtime.h>

// Problem constants
#define NB 16
#define DD 256
#define LL 2048
#define KK 8192
#define NN (NB*LL)        // 32768 vectors
#define NTOT (NB*DD*LL)   // 8388608 output elements

// Scratch (device globals: no allocations allowed)
__device__ float  g_z2[NN];
__device__ float  g_e2[KK];
__device__ int    g_idx[NN];
__device__ double g_loss;

__global__ void reset_kernel() { g_loss = 0.0; }

// e2[k] = sum_d cb[k][d]^2  (order-insensitive: e2 rounds away in z2+e2)
__global__ void e2_kernel(const float* __restrict__ cb) {
    int warp = blockIdx.x * 8 + (threadIdx.x >> 5);
    int lane = threadIdx.x & 31;
    const float* r = cb + (size_t)warp * DD;
    float s = 0.f;
#pragma unroll
    for (int i = 0; i < DD / 32; i++) {
        float v = r[lane + i * 32];
        s = fmaf(v, v, s);
    }
#pragma unroll
    for (int o = 16; o > 0; o >>= 1) s += __shfl_down_sync(0xffffffffu, s, o);
    if (lane == 0) g_e2[warp] = s;
}

// z2[n] = sum_d z[b][d][l]^2 — MUST be sequential-d, separate mul/add roundings
// (hypothesized match for XLA's strided-reduction lowering).
__global__ void z2_kernel(const float* __restrict__ z) {
    int n = blockIdx.x * 256 + threadIdx.x;
    int b = n >> 11, l = n & 2047;
    const float* p = z + (size_t)b * (DD * LL) + l;
    float s = 0.f;
#pragma unroll 8
    for (int d = 0; d < DD; d++) {
        float v = p[(size_t)d * LL];
        s = __fadd_rn(s, __fmul_rn(v, v));
    }
    g_z2[n] = s;
}

// Fused GEMM + argmin.
// Block: 128 n x all K. Threads 256 as (tx 0..15 -> k, ty 0..15 -> n), 8x8 micro-tile.
// z tile [256 d][128 n] persisted in smem (128 KB); codebook staged per 32-d chunk (16 KB).
// Epilogue replicates reference rounding: s = fl( fl(z2 + e2) - 2*ez ).
__global__ __launch_bounds__(256) void vq_argmin_kernel(
    const float* __restrict__ z, const float* __restrict__ cb) {
    extern __shared__ float sm[];
    float* zs = sm;               // [256][128]
    float* cs = sm + DD * 128;    // [32][128]
    const int tid = threadIdx.x;
    const int tx = tid & 15, ty = tid >> 4;
    const int n0 = blockIdx.x * 128;
    const int b = n0 >> 11, l0 = n0 & 2047;
    const float* zb = z + (size_t)b * (DD * LL) + l0;

    // Stage z tile: zs[d][n_local]
    for (int i = tid; i < DD * 32; i += 256) {
        int d = i >> 5, v = (i & 31) << 2;
        *reinterpret_cast<float4*>(&zs[d * 128 + v]) =
            *reinterpret_cast<const float4*>(&zb[(size_t)d * LL + v]);
    }

    float z2r[8];
#pragma unroll
    for (int i = 0; i < 8; i++) z2r[i] = g_z2[n0 + ty * 8 + i];

    float bestV[8];
    int   bestI[8];
#pragma unroll
    for (int i = 0; i < 8; i++) { bestV[i] = 3.4e38f; bestI[i] = 0; }

    for (int kt = 0; kt < KK / 128; kt++) {
        const int k0 = kt * 128;
        float acc[8][8];
#pragma unroll
        for (int i = 0; i < 8; i++)
#pragma unroll
            for (int j = 0; j < 8; j++) acc[i][j] = 0.f;

        for (int dc = 0; dc < 8; dc++) {
            const int dB = dc * 32;
            __syncthreads();   // previous chunk's cs reads done
            // Stage codebook chunk transposed: cs[d][k_local]
            for (int i = tid; i < 1024; i += 256) {
                int kr = i >> 3, d4 = (i & 7) << 2;
                float4 c = *reinterpret_cast<const float4*>(
                    &cb[(size_t)(k0 + kr) * DD + dB + d4]);
                cs[(d4 + 0) * 128 + kr] = c.x;
                cs[(d4 + 1) * 128 + kr] = c.y;
                cs[(d4 + 2) * 128 + kr] = c.z;
                cs[(d4 + 3) * 128 + kr] = c.w;
            }
            __syncthreads();
#pragma unroll 8
            for (int d = 0; d < 32; d++) {
                float zr[8], cr[8];
                *reinterpret_cast<float4*>(&zr[0]) =
                    *reinterpret_cast<const float4*>(&zs[(dB + d) * 128 + ty * 8]);
                *reinterpret_cast<float4*>(&zr[4]) =
                    *reinterpret_cast<const float4*>(&zs[(dB + d) * 128 + ty * 8 + 4]);
                *reinterpret_cast<float4*>(&cr[0]) =
                    *reinterpret_cast<const float4*>(&cs[d * 128 + tx * 8]);
                *reinterpret_cast<float4*>(&cr[4]) =
                    *reinterpret_cast<const float4*>(&cs[d * 128 + tx * 8 + 4]);
#pragma unroll
                for (int i = 0; i < 8; i++)
#pragma unroll
                    for (int j = 0; j < 8; j++)
                        acc[i][j] = fmaf(zr[i], cr[j], acc[i][j]);
            }
        }
        // Epilogue: exact reference rounding + running argmin (k ascending, strict <)
#pragma unroll
        for (int j = 0; j < 8; j++) {
            int k = k0 + tx * 8 + j;
            float e2v = g_e2[k];
#pragma unroll
            for (int i = 0; i < 8; i++) {
                float t = __fadd_rn(z2r[i], e2v);
                float s = __fadd_rn(t, -2.0f * acc[i][j]);
                if (s < bestV[i]) { bestV[i] = s; bestI[i] = k; }
            }
        }
    }

    __syncthreads();
    // Cross-tx reduction (reuse cs region): tie-break by smaller index
    float* rv = cs;
    int*   ri = reinterpret_cast<int*>(cs + 2048);
#pragma unroll
    for (int i = 0; i < 8; i++) {
        rv[(ty * 8 + i) * 16 + tx] = bestV[i];
        ri[(ty * 8 + i) * 16 + tx] = bestI[i];
    }
    __syncthreads();
    if (tid < 128) {
        float bv = rv[tid * 16];
        int   bi = ri[tid * 16];
#pragma unroll
        for (int t = 1; t < 16; t++) {
            float v = rv[tid * 16 + t];
            int  ii = ri[tid * 16 + t];
            if (v < bv || (v == bv && ii < bi)) { bv = v; bi = ii; }
        }
        g_idx[n0 + tid] = bi;
    }
}

// Output (straight-through, replicating both fp32 roundings) + loss accumulation.
__global__ void out_loss_kernel(const float* __restrict__ z,
                                const float* __restrict__ cb,
                                float* __restrict__ out) {
    double acc = 0.0;
    int stride = gridDim.x * blockDim.x;
    for (int e = blockIdx.x * blockDim.x + threadIdx.x; e < NTOT; e += stride) {
        int l = e & 2047;
        int d = (e >> 11) & 255;
        int b = e >> 19;
        int id = g_idx[(b << 11) | l];
        float ze = z[e];
        float zq = cb[(size_t)id * DD + d];
        float df = __fsub_rn(zq, ze);          // fl(z_q - z_e)
        out[e] = __fadd_rn(ze, df);            // fl(z_e + fl(z_q - z_e))
        float sq = __fmul_rn(df, df);
        acc += (double)sq;
    }
#pragma unroll
    for (int o = 16; o > 0; o >>= 1) acc += __shfl_down_sync(0xffffffffu, acc, o);
    __shared__ double red[8];
    int lane = threadIdx.x & 31, w = threadIdx.x >> 5;
    if (lane == 0) red[w] = acc;
    __syncthreads();
    if (w == 0) {
        double v = (lane < 8) ? red[lane] : 0.0;
#pragma unroll
        for (int o = 4; o > 0; o >>= 1) v += __shfl_down_sync(0xffffffffu, v, o);
        if (lane == 0) atomicAdd(&g_loss, v);
    }
}

__global__ void finalize_kernel(float* __restrict__ out, int out_size) {
    double m = g_loss / (double)NTOT;
    float mf = (float)m;                               // mean((z_q - z_e)^2)
    float vq = __fadd_rn(__fmul_rn(mf, 0.25f), mf);    // commitment*0.25 + embedding
    if (out_size > NTOT) out[NTOT] = vq;
}

extern "C" void kernel_launch(void* const* d_in, const int* in_sizes, int n_in,
                              void* d_out, int out_size) {
    const float* z  = (const float*)d_in[0];
    const float* cb = (const float*)d_in[1];
    float* out = (float*)d_out;

    cudaFuncSetAttribute(vq_argmin_kernel,
                         cudaFuncAttributeMaxDynamicSharedMemorySize,
                         (DD * 128 + 32 * 128) * 4);

    reset_kernel<<<1, 1>>>();
    e2_kernel<<<KK / 8, 256>>>(cb);
    z2_kernel<<<NN / 256, 256>>>(z);
    vq_argmin_kernel<<<NN / 128, 256, (DD * 128 + 32 * 128) * 4>>>(z, cb);
    out_loss_kernel<<<1184, 256>>>(z, cb, out);
    finalize_kernel<<<1, 1>>>(out, out_size);
}

// round 5
// speedup vs baseline: 1.9132x; 1.9132x over previous
#include <cuda_runtime.h>
#include <cstdint>

#define NB 16
#define DD 256
#define LL 2048
#define KK 8192
#define NN (NB*LL)        // 32768 z vectors
#define NTOT (NB*DD*LL)   // 8388608 output elements
#define KS 512            // hi/lo interleaved contraction length
#define BM 256
#define BN 128
#define BK 32
#define NKITER (KS/BK)    // 16
#define ASTRIDE 36
#define A_FLOATS (BM*ASTRIDE)
#define B_FLOATS (BN*ASTRIDE)
#define STAGE_FLOATS (A_FLOATS+B_FLOATS)
#define STAGE_BYTES (STAGE_FLOATS*4)
#define NSTAGE 3
#define DYNSMEM (NSTAGE*STAGE_BYTES)      // 165888
#define NGRP 256                          // 32-code groups per n
#define RESCUE_MARGIN 8e-5f

// ---------------- device scratch ----------------
__device__ __align__(1024) float g_zS[(size_t)NN*KS];   // 64MB split z  [n][k]
__device__ __align__(1024) float g_cbS[(size_t)KK*KS];  // 16MB split cb [k][k]
__device__ unsigned long long g_grp[(size_t)NN*NGRP];   // 67MB per-group packed minima
__device__ float  g_z2[NN];
__device__ float  g_e2[KK];
__device__ int    g_idx[NN];
__device__ double g_loss;

// ---------------- helpers ----------------
__device__ __forceinline__ uint32_t smem_u32(const void* p) {
    uint32_t a;
    asm("{ .reg .u64 t; cvta.to.shared.u64 t, %1; cvt.u32.u64 %0, t; }" : "=r"(a) : "l"(p));
    return a;
}
__device__ __forceinline__ float tf32_rn(float x) {
    uint32_t u; asm("cvt.rna.tf32.f32 %0, %1;" : "=r"(u) : "f"(x));
    return __uint_as_float(u);
}
#define CP_ASYNC16(sa, gp) \
    asm volatile("cp.async.cg.shared.global [%0], [%1], 16;" :: "r"(sa), "l"(gp) : "memory")
#define CP_COMMIT() asm volatile("cp.async.commit_group;" ::: "memory")
#define CP_WAIT1()  asm volatile("cp.async.wait_group 1;" ::: "memory")
#define CP_WAIT0()  asm volatile("cp.async.wait_group 0;" ::: "memory")

__device__ __forceinline__ void mma_tf32(float* c, const uint32_t* a, const uint32_t* b) {
    asm volatile(
        "mma.sync.aligned.m16n8k8.row.col.f32.tf32.tf32.f32 "
        "{%0,%1,%2,%3}, {%4,%5,%6,%7}, {%8,%9}, {%0,%1,%2,%3};"
        : "+f"(c[0]), "+f"(c[1]), "+f"(c[2]), "+f"(c[3])
        : "r"(a[0]), "r"(a[1]), "r"(a[2]), "r"(a[3]), "r"(b[0]), "r"(b[1]));
}

// ---------------- small kernels (bit-exact numerics, validated R2) ----------------
__global__ void reset_kernel() { g_loss = 0.0; }

__global__ void e2_kernel(const float* __restrict__ cb) {
    int warp = blockIdx.x * 8 + (threadIdx.x >> 5);
    int lane = threadIdx.x & 31;
    const float* r = cb + (size_t)warp * DD;
    float s = 0.f;
#pragma unroll
    for (int i = 0; i < DD / 32; i++) { float v = r[lane + i * 32]; s = fmaf(v, v, s); }
#pragma unroll
    for (int o = 16; o > 0; o >>= 1) s += __shfl_down_sync(0xffffffffu, s, o);
    if (lane == 0) g_e2[warp] = s;
}

__global__ void z2_kernel(const float* __restrict__ z) {
    int n = blockIdx.x * 256 + threadIdx.x;
    int b = n >> 11, l = n & 2047;
    const float* p = z + (size_t)b * (DD * LL) + l;
    float s = 0.f;
#pragma unroll 8
    for (int d = 0; d < DD; d++) {
        float v = p[(size_t)d * LL];
        s = __fadd_rn(s, __fmul_rn(v, v));
    }
    g_z2[n] = s;
}

__global__ void split_cb_kernel(const float* __restrict__ cb) {
    int i = blockIdx.x * 256 + threadIdx.x;
    float x = cb[i];
    float h = tf32_rn(x);
    float l = tf32_rn(__fsub_rn(x, h));
    int k = i >> 8, d = i & 255;
    *reinterpret_cast<float2*>(&g_cbS[(size_t)k * KS + 2 * d]) = make_float2(h, l);
}

__global__ void split_z_kernel(const float* __restrict__ z) {
    int gid = blockIdx.x * 256 + threadIdx.x;
    int n  = gid & (NN - 1);
    int d0 = (gid >> 15) << 2;
    int b = n >> 11, l = n & 2047;
    const float* p = z + ((size_t)b * DD + d0) * LL + l;
    float x0 = p[0], x1 = p[LL], x2 = p[2 * LL], x3 = p[3 * LL];
    float h0 = tf32_rn(x0), l0 = tf32_rn(__fsub_rn(x0, h0));
    float h1 = tf32_rn(x1), l1 = tf32_rn(__fsub_rn(x1, h1));
    float h2 = tf32_rn(x2), l2 = tf32_rn(__fsub_rn(x2, h2));
    float h3 = tf32_rn(x3), l3 = tf32_rn(__fsub_rn(x3, h3));
    float4* o = reinterpret_cast<float4*>(&g_zS[(size_t)n * KS + 2 * d0]);
    o[0] = make_float4(h0, l0, h1, l1);
    o[1] = make_float4(h2, l2, h3, l3);
}

// ---------------- main GEMM (mma.sync tf32, hi/lo split) ----------------
__device__ __forceinline__ void stage_load(float* buf, int m0, int n0, int kk0, int tid) {
#pragma unroll
    for (int it = 0; it < 8; it++) {
        int idx = tid + it * 256;
        int row = idx >> 3, ch = (idx & 7) << 2;
        uint32_t sa = smem_u32(buf + row * ASTRIDE + ch);
        CP_ASYNC16(sa, &g_zS[(size_t)(m0 + row) * KS + kk0 + ch]);
    }
#pragma unroll
    for (int it = 0; it < 4; it++) {
        int idx = tid + it * 256;
        int row = idx >> 3, ch = (idx & 7) << 2;
        uint32_t sa = smem_u32(buf + A_FLOATS + row * ASTRIDE + ch);
        CP_ASYNC16(sa, &g_cbS[(size_t)(n0 + row) * KS + kk0 + ch]);
    }
}

__global__ __launch_bounds__(256, 1) void vq_mma_kernel() {
    extern __shared__ __align__(16) float dsm[];
    const int tid = threadIdx.x;
    const int wid = tid >> 5, lane = tid & 31;
    const int warpM = wid >> 1, warpN = wid & 1;
    const int q = lane >> 2, r = lane & 3;
    const int m0 = blockIdx.x * BM;
    const int n0 = blockIdx.y * BN;

    float c[4][8][4];
#pragma unroll
    for (int i = 0; i < 4; i++)
#pragma unroll
        for (int j = 0; j < 8; j++)
#pragma unroll
            for (int t = 0; t < 4; t++) c[i][j][t] = 0.f;

    stage_load(dsm, m0, n0, 0, tid); CP_COMMIT();
    stage_load(dsm + STAGE_FLOATS, m0, n0, BK, tid); CP_COMMIT();

    for (int i = 0; i < NKITER; i++) {
        if (i < NKITER - 1) CP_WAIT1(); else CP_WAIT0();
        __syncthreads();
        if (i + 2 < NKITER) {
            stage_load(dsm + ((i + 2) % NSTAGE) * STAGE_FLOATS, m0, n0, (i + 2) * BK, tid);
            CP_COMMIT();
        }
        const float* As = dsm + (i % NSTAGE) * STAGE_FLOATS;
        const float* Bs = As + A_FLOATS;
#pragma unroll
        for (int kb = 0; kb < BK; kb += 8) {
            uint32_t a[4][4], b[8][2];
#pragma unroll
            for (int mf = 0; mf < 4; mf++) {
                int r0 = warpM * 64 + mf * 16 + q;
                a[mf][0] = __float_as_uint(As[r0 * ASTRIDE + kb + r]);
                a[mf][1] = __float_as_uint(As[(r0 + 8) * ASTRIDE + kb + r]);
                a[mf][2] = __float_as_uint(As[r0 * ASTRIDE + kb + 4 + r]);
                a[mf][3] = __float_as_uint(As[(r0 + 8) * ASTRIDE + kb + 4 + r]);
            }
#pragma unroll
            for (int nf = 0; nf < 8; nf++) {
                int cc = warpN * 64 + nf * 8 + q;
                b[nf][0] = __float_as_uint(Bs[cc * ASTRIDE + kb + r]);
                b[nf][1] = __float_as_uint(Bs[cc * ASTRIDE + kb + 4 + r]);
            }
#pragma unroll
            for (int mf = 0; mf < 4; mf++)
#pragma unroll
                for (int nf = 0; nf < 8; nf++)
                    mma_tf32(c[mf][nf], a[mf], b[nf]);
        }
        __syncthreads();
    }

    // ---- epilogue: per-(row, 32-code group) packed minima -> g_grp ----
#pragma unroll
    for (int mf = 0; mf < 4; mf++) {
#pragma unroll
        for (int half = 0; half < 2; half++) {
            int lrow = warpM * 64 + mf * 16 + q + half * 8;
            float z2v = g_z2[m0 + lrow];
#pragma unroll
            for (int nfh = 0; nfh < 2; nfh++) {
                unsigned long long best = ~0ull;
#pragma unroll
                for (int nfo = 0; nfo < 4; nfo++) {
                    int nf = nfh * 4 + nfo;
                    int k0 = n0 + warpN * 64 + nf * 8 + 2 * r;
                    float e20 = __ldg(&g_e2[k0]);
                    float e21 = __ldg(&g_e2[k0 + 1]);
                    float ez0 = c[mf][nf][half * 2 + 0];
                    float ez1 = c[mf][nf][half * 2 + 1];
                    float s0 = __fadd_rn(__fadd_rn(z2v, e20), -2.0f * ez0);
                    float s1 = __fadd_rn(__fadd_rn(z2v, e21), -2.0f * ez1);
                    unsigned long long p0 = ((unsigned long long)__float_as_uint(s0) << 32) | (unsigned)k0;
                    unsigned long long p1 = ((unsigned long long)__float_as_uint(s1) << 32) | (unsigned)(k0 + 1);
                    if (p0 < best) best = p0;
                    if (p1 < best) best = p1;
                }
#pragma unroll
                for (int off = 1; off < 4; off <<= 1) {
                    unsigned long long o = __shfl_xor_sync(0xffffffffu, best, off);
                    if (o < best) best = o;
                }
                if (r == 0)
                    g_grp[(size_t)(m0 + lrow) * NGRP + blockIdx.y * 4 + warpN * 2 + nfh] = best;
            }
        }
    }
}

// ---------------- rescue: exact re-score of near-min groups (R2 chain) ----------------
__global__ __launch_bounds__(256) void rescue_kernel(const float* __restrict__ z,
                                                     const float* __restrict__ cb) {
    const int lane = threadIdx.x & 31;
    const int n = blockIdx.x * 8 + (threadIdx.x >> 5);
    const unsigned long long* base = g_grp + (size_t)n * NGRP;

    unsigned long long gm[8];
    unsigned long long mn = ~0ull;
#pragma unroll
    for (int j = 0; j < 8; j++) {
        gm[j] = base[lane + 32 * j];
        if (gm[j] < mn) mn = gm[j];
    }
#pragma unroll
    for (int off = 16; off > 0; off >>= 1) {
        unsigned long long o = __shfl_xor_sync(0xffffffffu, mn, off);
        if (o < mn) mn = o;
    }
    const float T = __uint_as_float((unsigned)(mn >> 32)) + RESCUE_MARGIN;

    const int b = n >> 11, l = n & 2047;
    const float z2v = g_z2[n];
    const float* zp = z + (size_t)b * (DD * LL) + l;
    unsigned long long best = ~0ull;

#pragma unroll
    for (int j = 0; j < 8; j++) {
        unsigned flag = __ballot_sync(0xffffffffu,
                                      __uint_as_float((unsigned)(gm[j] >> 32)) <= T);
        while (flag) {
            int g = 32 * j + (__ffs(flag) - 1);
            flag &= flag - 1;
            int k = g * 32 + lane;
            const float4* crow = reinterpret_cast<const float4*>(cb + (size_t)k * DD);
            float acc = 0.f;
            const float* zq = zp;
#pragma unroll 4
            for (int d4 = 0; d4 < DD / 4; d4++) {
                float4 c4 = __ldg(&crow[d4]);
                float za = zq[0], zb = zq[LL], zc = zq[2 * LL], zd = zq[3 * LL];
                acc = fmaf(za, c4.x, acc);
                acc = fmaf(zb, c4.y, acc);
                acc = fmaf(zc, c4.z, acc);
                acc = fmaf(zd, c4.w, acc);
                zq += 4 * LL;
            }
            float s = __fadd_rn(__fadd_rn(z2v, g_e2[k]), -2.0f * acc);
            unsigned long long p = ((unsigned long long)__float_as_uint(s) << 32) | (unsigned)k;
            if (p < best) best = p;
        }
    }
#pragma unroll
    for (int off = 16; off > 0; off >>= 1) {
        unsigned long long o = __shfl_xor_sync(0xffffffffu, best, off);
        if (o < best) best = o;
    }
    if (lane == 0) g_idx[n] = (int)(best & 0xFFFFFFFFull);
}

// ---------------- output + loss (bit-exact) ----------------
__global__ void out_loss_kernel(const float* __restrict__ z,
                                const float* __restrict__ cb,
                                float* __restrict__ out) {
    double acc = 0.0;
    int stride = gridDim.x * blockDim.x;
    for (int e = blockIdx.x * blockDim.x + threadIdx.x; e < NTOT; e += stride) {
        int l = e & 2047;
        int d = (e >> 11) & 255;
        int b = e >> 19;
        int id = g_idx[(b << 11) | l];
        float ze = z[e];
        float zq = cb[(size_t)id * DD + d];
        float df = __fsub_rn(zq, ze);
        out[e] = __fadd_rn(ze, df);
        acc += (double)__fmul_rn(df, df);
    }
#pragma unroll
    for (int o = 16; o > 0; o >>= 1) acc += __shfl_down_sync(0xffffffffu, acc, o);
    __shared__ double red[8];
    int lane = threadIdx.x & 31, w = threadIdx.x >> 5;
    if (lane == 0) red[w] = acc;
    __syncthreads();
    if (w == 0) {
        double v = (lane < 8) ? red[lane] : 0.0;
#pragma unroll
        for (int o = 4; o > 0; o >>= 1) v += __shfl_down_sync(0xffffffffu, v, o);
        if (lane == 0) atomicAdd(&g_loss, v);
    }
}

__global__ void finalize_kernel(float* __restrict__ out, int out_size) {
    double m = g_loss / (double)NTOT;
    float mf = (float)m;
    float vq = __fadd_rn(__fmul_rn(mf, 0.25f), mf);
    if (out_size > NTOT) out[NTOT] = vq;
}

// ---------------- host ----------------
extern "C" void kernel_launch(void* const* d_in, const int* in_sizes, int n_in,
                              void* d_out, int out_size) {
    const float* z  = (const float*)d_in[0];
    const float* cb = (const float*)d_in[1];
    float* out = (float*)d_out;

    cudaFuncSetAttribute(vq_mma_kernel, cudaFuncAttributeMaxDynamicSharedMemorySize, DYNSMEM);

    reset_kernel<<<1, 1>>>();
    e2_kernel<<<KK / 8, 256>>>(cb);
    z2_kernel<<<NN / 256, 256>>>(z);
    split_cb_kernel<<<KK * DD / 256, 256>>>(cb);
    split_z_kernel<<<NN * (DD / 4) / 256, 256>>>(z);
    dim3 grid(NN / BM, KK / BN);
    vq_mma_kernel<<<grid, 256, DYNSMEM>>>();
    rescue_kernel<<<NN / 8, 256>>>(z, cb);
    out_loss_kernel<<<1184, 256>>>(z, cb, out);
    finalize_kernel<<<1, 1>>>(out, out_size);
}

// round 6
// speedup vs baseline: 3.9278x; 2.0530x over previous
#include <cuda_runtime.h>
#include <cuda_fp16.h>
#include <cstdint>

#define NB 16
#define DD 256
#define LL 2048
#define KK 8192
#define NN (NB*LL)        // 32768 z vectors
#define NTOT (NB*DD*LL)
#define BM 256
#define BN 128
#define BKH 64            // k halves per stage
#define NKITER (DD/BKH)   // 4
#define HSTRIDE 72        // padded halves per row (144B, conflict-free)
#define A_HALFS (BM*HSTRIDE)
#define B_HALFS (BN*HSTRIDE)
#define STAGE_HALFS (A_HALFS+B_HALFS)
#define STAGE_BYTES (STAGE_HALFS*2)       // 55296
#define NSTAGE 3
#define DYNSMEM (NSTAGE*STAGE_BYTES)      // 165888
#define NGRP 256
#define RESCUE_MARGIN 2e-4f
#define EZ_UNSCALE (-0.000244140625f)     // -2 * 2^-13 (exact)

// ---------------- device scratch ----------------
__device__ __align__(1024) __half g_zH[(size_t)NN*DD];  // 16MB fp16 z   [n][d]
__device__ __align__(1024) __half g_cH[(size_t)KK*DD];  // 4MB fp16 cb*8192 [k][d]
__device__ unsigned long long g_grp[(size_t)NN*NGRP];   // per-group packed minima
__device__ float  g_z2[NN];
__device__ float  g_e2[KK];
__device__ int    g_idx[NN];
__device__ double g_loss;

// ---------------- helpers ----------------
__device__ __forceinline__ uint32_t smem_u32(const void* p) {
    uint32_t a;
    asm("{ .reg .u64 t; cvta.to.shared.u64 t, %1; cvt.u32.u64 %0, t; }" : "=r"(a) : "l"(p));
    return a;
}
#define CP_ASYNC16(sa, gp) \
    asm volatile("cp.async.cg.shared.global [%0], [%1], 16;" :: "r"(sa), "l"(gp) : "memory")
#define CP_COMMIT() asm volatile("cp.async.commit_group;" ::: "memory")
#define CP_WAIT1()  asm volatile("cp.async.wait_group 1;" ::: "memory")
#define CP_WAIT0()  asm volatile("cp.async.wait_group 0;" ::: "memory")

__device__ __forceinline__ void mma_f16(float* c, const uint32_t* a, const uint32_t* b) {
    asm volatile(
        "mma.sync.aligned.m16n8k16.row.col.f32.f16.f16.f32 "
        "{%0,%1,%2,%3}, {%4,%5,%6,%7}, {%8,%9}, {%0,%1,%2,%3};"
        : "+f"(c[0]), "+f"(c[1]), "+f"(c[2]), "+f"(c[3])
        : "r"(a[0]), "r"(a[1]), "r"(a[2]), "r"(a[3]), "r"(b[0]), "r"(b[1]));
}

// ---------------- prep / small kernels (R2-validated numerics) ----------------
__global__ void reset_kernel() { g_loss = 0.0; }

__global__ void e2_kernel(const float* __restrict__ cb) {
    int warp = blockIdx.x * 8 + (threadIdx.x >> 5);
    int lane = threadIdx.x & 31;
    const float* r = cb + (size_t)warp * DD;
    float s = 0.f;
#pragma unroll
    for (int i = 0; i < DD / 32; i++) { float v = r[lane + i * 32]; s = fmaf(v, v, s); }
#pragma unroll
    for (int o = 16; o > 0; o >>= 1) s += __shfl_down_sync(0xffffffffu, s, o);
    if (lane == 0) g_e2[warp] = s;
}

__global__ void z2_kernel(const float* __restrict__ z) {
    int n = blockIdx.x * 256 + threadIdx.x;
    int b = n >> 11, l = n & 2047;
    const float* p = z + (size_t)b * (DD * LL) + l;
    float s = 0.f;
#pragma unroll 8
    for (int d = 0; d < DD; d++) {
        float v = p[(size_t)d * LL];
        s = __fadd_rn(s, __fmul_rn(v, v));
    }
    g_z2[n] = s;
}

__global__ void prep_c_kernel(const float* __restrict__ cb) {
    int i = blockIdx.x * 256 + threadIdx.x;       // over KK*DD/4
    float4 v = reinterpret_cast<const float4*>(cb)[i];
    __half2 h0 = __floats2half2_rn(v.x * 8192.f, v.y * 8192.f);
    __half2 h1 = __floats2half2_rn(v.z * 8192.f, v.w * 8192.f);
    reinterpret_cast<__half2*>(g_cH)[i * 2]     = h0;
    reinterpret_cast<__half2*>(g_cH)[i * 2 + 1] = h1;
}

__global__ void prep_z_kernel(const float* __restrict__ z) {
    int gid = blockIdx.x * 256 + threadIdx.x;     // NN*64 threads
    int n  = gid & (NN - 1);
    int d0 = (gid >> 15) << 2;
    int b = n >> 11, l = n & 2047;
    const float* p = z + ((size_t)b * DD + d0) * LL + l;
    float x0 = p[0], x1 = p[LL], x2 = p[2 * LL], x3 = p[3 * LL];
    __half2* o = reinterpret_cast<__half2*>(&g_zH[(size_t)n * DD + d0]);
    o[0] = __floats2half2_rn(x0, x1);
    o[1] = __floats2half2_rn(x2, x3);
}

// ---------------- main GEMM (fp16 mma.sync) ----------------
__device__ __forceinline__ void stage_load(__half* buf, int m0, int n0, int kk0, int tid) {
#pragma unroll
    for (int it = 0; it < 8; it++) {              // A: 256 rows x 128B
        int idx = tid + it * 256;
        int row = idx >> 3, ch = (idx & 7) << 3;
        uint32_t sa = smem_u32(buf + row * HSTRIDE + ch);
        CP_ASYNC16(sa, &g_zH[(size_t)(m0 + row) * DD + kk0 + ch]);
    }
#pragma unroll
    for (int it = 0; it < 4; it++) {              // B: 128 rows x 128B
        int idx = tid + it * 256;
        int row = idx >> 3, ch = (idx & 7) << 3;
        uint32_t sa = smem_u32(buf + A_HALFS + row * HSTRIDE + ch);
        CP_ASYNC16(sa, &g_cH[(size_t)(n0 + row) * DD + kk0 + ch]);
    }
}

__global__ __launch_bounds__(256, 1) void vq_mma_kernel() {
    extern __shared__ __align__(16) __half hsm[];
    const int tid = threadIdx.x;
    const int wid = tid >> 5, lane = tid & 31;
    const int warpM = wid >> 1, warpN = wid & 1;
    const int q = lane >> 2, r = lane & 3;
    const int m0 = blockIdx.x * BM;
    const int n0 = blockIdx.y * BN;

    float c[4][8][4];
#pragma unroll
    for (int i = 0; i < 4; i++)
#pragma unroll
        for (int j = 0; j < 8; j++)
#pragma unroll
            for (int t = 0; t < 4; t++) c[i][j][t] = 0.f;

    stage_load(hsm, m0, n0, 0, tid); CP_COMMIT();
    stage_load(hsm + STAGE_HALFS, m0, n0, BKH, tid); CP_COMMIT();

    for (int i = 0; i < NKITER; i++) {
        if (i < NKITER - 1) CP_WAIT1(); else CP_WAIT0();
        __syncthreads();
        if (i + 2 < NKITER) {
            stage_load(hsm + ((i + 2) % NSTAGE) * STAGE_HALFS, m0, n0, (i + 2) * BKH, tid);
            CP_COMMIT();
        }
        const __half* As = hsm + (i % NSTAGE) * STAGE_HALFS;
        const __half* Bs = As + A_HALFS;
#pragma unroll
        for (int kb = 0; kb < BKH; kb += 16) {
            uint32_t a[4][4], b[8][2];
#pragma unroll
            for (int mf = 0; mf < 4; mf++) {
                int r0 = warpM * 64 + mf * 16 + q;
                a[mf][0] = *reinterpret_cast<const uint32_t*>(&As[r0 * HSTRIDE + kb + 2 * r]);
                a[mf][1] = *reinterpret_cast<const uint32_t*>(&As[(r0 + 8) * HSTRIDE + kb + 2 * r]);
                a[mf][2] = *reinterpret_cast<const uint32_t*>(&As[r0 * HSTRIDE + kb + 2 * r + 8]);
                a[mf][3] = *reinterpret_cast<const uint32_t*>(&As[(r0 + 8) * HSTRIDE + kb + 2 * r + 8]);
            }
#pragma unroll
            for (int nf = 0; nf < 8; nf++) {
                int cc = warpN * 64 + nf * 8 + q;
                b[nf][0] = *reinterpret_cast<const uint32_t*>(&Bs[cc * HSTRIDE + kb + 2 * r]);
                b[nf][1] = *reinterpret_cast<const uint32_t*>(&Bs[cc * HSTRIDE + kb + 2 * r + 8]);
            }
#pragma unroll
            for (int mf = 0; mf < 4; mf++)
#pragma unroll
                for (int nf = 0; nf < 8; nf++)
                    mma_f16(c[mf][nf], a[mf], b[nf]);
        }
        __syncthreads();
    }

    // ---- epilogue: per-(row, 32-code group) packed minima -> g_grp ----
    // ez = acc * 2^-13 (exact); s = fl( fl(z2+e2) + acc * (-2*2^-13) )
#pragma unroll
    for (int mf = 0; mf < 4; mf++) {
#pragma unroll
        for (int half = 0; half < 2; half++) {
            int lrow = warpM * 64 + mf * 16 + q + half * 8;
            float z2v = g_z2[m0 + lrow];
#pragma unroll
            for (int nfh = 0; nfh < 2; nfh++) {
                unsigned long long best = ~0ull;
#pragma unroll
                for (int nfo = 0; nfo < 4; nfo++) {
                    int nf = nfh * 4 + nfo;
                    int k0 = n0 + warpN * 64 + nf * 8 + 2 * r;
                    float e20 = __ldg(&g_e2[k0]);
                    float e21 = __ldg(&g_e2[k0 + 1]);
                    float s0 = __fadd_rn(__fadd_rn(z2v, e20), c[mf][nf][half * 2 + 0] * EZ_UNSCALE);
                    float s1 = __fadd_rn(__fadd_rn(z2v, e21), c[mf][nf][half * 2 + 1] * EZ_UNSCALE);
                    unsigned long long p0 = ((unsigned long long)__float_as_uint(s0) << 32) | (unsigned)k0;
                    unsigned long long p1 = ((unsigned long long)__float_as_uint(s1) << 32) | (unsigned)(k0 + 1);
                    if (p0 < best) best = p0;
                    if (p1 < best) best = p1;
                }
#pragma unroll
                for (int off = 1; off < 4; off <<= 1) {
                    unsigned long long o = __shfl_xor_sync(0xffffffffu, best, off);
                    if (o < best) best = o;
                }
                if (r == 0)
                    g_grp[(size_t)(m0 + lrow) * NGRP + blockIdx.y * 4 + warpN * 2 + nfh] = best;
            }
        }
    }
}

// ---------------- rescue: exact re-score of near-min groups (bit-exact R2 chain) ----------------
__global__ __launch_bounds__(256) void rescue_kernel(const float* __restrict__ z,
                                                     const float* __restrict__ cb) {
    const int lane = threadIdx.x & 31;
    const int n = blockIdx.x * 8 + (threadIdx.x >> 5);
    const unsigned long long* base = g_grp + (size_t)n * NGRP;

    unsigned long long gm[8];
    unsigned long long mn = ~0ull;
#pragma unroll
    for (int j = 0; j < 8; j++) {
        gm[j] = base[lane + 32 * j];
        if (gm[j] < mn) mn = gm[j];
    }
#pragma unroll
    for (int off = 16; off > 0; off >>= 1) {
        unsigned long long o = __shfl_xor_sync(0xffffffffu, mn, off);
        if (o < mn) mn = o;
    }
    const float T = __uint_as_float((unsigned)(mn >> 32)) + RESCUE_MARGIN;

    const int b = n >> 11, l = n & 2047;
    const float z2v = g_z2[n];
    const float* zp = z + (size_t)b * (DD * LL) + l;
    unsigned long long best = ~0ull;

#pragma unroll
    for (int j = 0; j < 8; j++) {
        unsigned flag = __ballot_sync(0xffffffffu,
                                      __uint_as_float((unsigned)(gm[j] >> 32)) <= T);
        while (flag) {
            int g = 32 * j + (__ffs(flag) - 1);
            flag &= flag - 1;
            int k = g * 32 + lane;
            const float4* crow = reinterpret_cast<const float4*>(cb + (size_t)k * DD);
            float acc = 0.f;
            const float* zq = zp;
#pragma unroll 4
            for (int d4 = 0; d4 < DD / 4; d4++) {
                float4 c4 = __ldg(&crow[d4]);
                float za = zq[0], zb = zq[LL], zc = zq[2 * LL], zd = zq[3 * LL];
                acc = fmaf(za, c4.x, acc);
                acc = fmaf(zb, c4.y, acc);
                acc = fmaf(zc, c4.z, acc);
                acc = fmaf(zd, c4.w, acc);
                zq += 4 * LL;
            }
            float s = __fadd_rn(__fadd_rn(z2v, g_e2[k]), -2.0f * acc);
            unsigned long long p = ((unsigned long long)__float_as_uint(s) << 32) | (unsigned)k;
            if (p < best) best = p;
        }
    }
#pragma unroll
    for (int off = 16; off > 0; off >>= 1) {
        unsigned long long o = __shfl_xor_sync(0xffffffffu, best, off);
        if (o < best) best = o;
    }
    if (lane == 0) g_idx[n] = (int)(best & 0xFFFFFFFFull);
}

// ---------------- output + loss (bit-exact) ----------------
__global__ void out_loss_kernel(const float* __restrict__ z,
                                const float* __restrict__ cb,
                                float* __restrict__ out) {
    double acc = 0.0;
    int stride = gridDim.x * blockDim.x;
    for (int e = blockIdx.x * blockDim.x + threadIdx.x; e < NTOT; e += stride) {
        int l = e & 2047;
        int d = (e >> 11) & 255;
        int b = e >> 19;
        int id = g_idx[(b << 11) | l];
        float ze = z[e];
        float zq = cb[(size_t)id * DD + d];
        float df = __fsub_rn(zq, ze);
        out[e] = __fadd_rn(ze, df);
        acc += (double)__fmul_rn(df, df);
    }
#pragma unroll
    for (int o = 16; o > 0; o >>= 1) acc += __shfl_down_sync(0xffffffffu, acc, o);
    __shared__ double red[8];
    int lane = threadIdx.x & 31, w = threadIdx.x >> 5;
    if (lane == 0) red[w] = acc;
    __syncthreads();
    if (w == 0) {
        double v = (lane < 8) ? red[lane] : 0.0;
#pragma unroll
        for (int o = 4; o > 0; o >>= 1) v += __shfl_down_sync(0xffffffffu, v, o);
        if (lane == 0) atomicAdd(&g_loss, v);
    }
}

__global__ void finalize_kernel(float* __restrict__ out, int out_size) {
    double m = g_loss / (double)NTOT;
    float mf = (float)m;
    float vq = __fadd_rn(__fmul_rn(mf, 0.25f), mf);
    if (out_size > NTOT) out[NTOT] = vq;
}

// ---------------- host ----------------
extern "C" void kernel_launch(void* const* d_in, const int* in_sizes, int n_in,
                              void* d_out, int out_size) {
    const float* z  = (const float*)d_in[0];
    const float* cb = (const float*)d_in[1];
    float* out = (float*)d_out;

    cudaFuncSetAttribute(vq_mma_kernel, cudaFuncAttributeMaxDynamicSharedMemorySize, DYNSMEM);

    reset_kernel<<<1, 1>>>();
    e2_kernel<<<KK / 8, 256>>>(cb);
    z2_kernel<<<NN / 256, 256>>>(z);
    prep_c_kernel<<<KK * DD / 4 / 256, 256>>>(cb);
    prep_z_kernel<<<NN * (DD / 4) / 256, 256>>>(z);
    dim3 grid(NN / BM, KK / BN);
    vq_mma_kernel<<<grid, 256, DYNSMEM>>>();
    rescue_kernel<<<NN / 8, 256>>>(z, cb);
    out_loss_kernel<<<1184, 256>>>(z, cb, out);
    finalize_kernel<<<1, 1>>>(out, out_size);
}